// round 14
// baseline (speedup 1.0000x reference)
#include <cuda_runtime.h>
#include <math.h>

#define N_   256
#define FB_  256
#define D_   64
#define H_   4
#define DH_  128
#define HD_  512
#define BD_  128
#define HBD_ 512
#define AK_  100
#define L_   4
#define EPS_ 1e-5f
#define G_   192   // persistent grid; all blocks co-resident (2/SM guaranteed)

// ---------------- scratch (device globals; zero-init, no allocations) ----------------
__device__ float g_d[N_ * N_];
__device__ unsigned char g_act[N_ * N_];
__device__ int   g_pairCount;
__device__ int   g_pairList[N_ * N_];
__device__ float g_diffs[L_ * H_ * N_ * N_];
__device__ float g_cdiffs[L_ * H_];
__device__ float g_q[N_ * D_];
__device__ float g_k[N_ * D_];
__device__ float g_pred0[N_];
__device__ float g_At[L_ * H_ * D_ * D_];      // [l][h][d][c] = Wq_h Wk_h^T / sqrt(DH)
__device__ float g_M[L_ * 2 * D_ * D_];        // [l][qk][d][c] effective update matrix
__device__ float g_v[L_ * 2 * D_];             // effective update bias
__device__ float g_bt[L_ * H_ * D_];           // [l][h][c]
__device__ float g_bpWT[L_ * HBD_ * BD_];      // transposed: [l][col(512)][c(128)]
__device__ float g_bowWT[(L_ - 1) * BD_ * HBD_]; // transposed: [l][cout(128)][o(512)]
__device__ float g_B[L_ * H_ * N_ * D_];       // [l][h][i][c]
__device__ float4 g_kT4[L_ * 16 * N_];         // [l][d4][j]
__device__ float g_colK[L_ * H_ * N_];         // [l][h][j]
__device__ float g_base[L_ * H_ * N_];         // attention affine constants
__device__ float g_w[L_ * H_ * N_];
__device__ unsigned g_barArrive;
__device__ unsigned g_barGen;

__device__ __forceinline__ float mishf(float x) {
    float sp = (x > 20.f) ? x : log1pf(expf(x));
    return x * tanhf(sp);
}

__device__ __forceinline__ void gridBar() {
    __threadfence();
    __syncthreads();
    if (threadIdx.x == 0) {
        unsigned gen = __ldcg(&g_barGen);
        unsigned t = atomicAdd(&g_barArrive, 1u);
        if (t == G_ - 1) {
            g_barArrive = 0u;
            __threadfence();
            atomicExch(&g_barGen, gen + 1u);
        } else {
            while (__ldcg(&g_barGen) == gen) __nanosleep(32);
        }
    }
    __syncthreads();
    __threadfence();
}

__global__ __launch_bounds__(512, 2)
void k_mega(const float* __restrict__ X, const float* __restrict__ E,
            const float* __restrict__ nt,
            const float* __restrict__ embW, const float* __restrict__ embB,
            const float* __restrict__ boutW, const float* __restrict__ boutB,
            const float* __restrict__ qpW, const float* __restrict__ qpB,
            const float* __restrict__ kpW, const float* __restrict__ kpB,
            const float* __restrict__ qoW, const float* __restrict__ qoB,
            const float* __restrict__ koW, const float* __restrict__ koB,
            const float* __restrict__ bpW, const float* __restrict__ bpB,
            const float* __restrict__ bowW, const float* __restrict__ bowB,
            const float* __restrict__ qlnG, const float* __restrict__ qlnB,
            const float* __restrict__ klnG, const float* __restrict__ klnB,
            float* __restrict__ out) {
    __shared__ __align__(16) char sm[20608];
    int b = blockIdx.x, tid = threadIdx.x;     // 512 threads

    // ============ Phase 0: blocks 0-127: embed/pred0/dist ; 128-191: PRE ============
    if (b < 128) {
        int half = tid >> 8, t = tid & 255;
        char* hb = sm + half * 2560;
        float* sx   = (float*)hb;
        float* se   = (float*)(hb + 1024);
        float* red  = (float*)(hb + 1440);
        float* wred = (float*)(hb + 2464);
        int i = 2 * b + half;
        sx[t] = X[i * FB_ + t];
        if (t < AK_) se[t] = E[i * AK_ + t];
        __syncthreads();
        // ---- distances: warp-cooperative, 16 lanes per j row (coalesced E reads) ----
        {
            int w8 = (t >> 5);
            int lane = t & 31;
            int sub = lane & 15, jh = lane >> 4;
            for (int pass = 0; pass < 16; pass++) {
                int j = pass * 16 + w8 * 2 + jh;
                float s = 0.f;
                const float* Ej = E + j * AK_;
#pragma unroll
                for (int k = sub; k < AK_; k += 16) { float d = se[k] - Ej[k]; s += d * d; }
#pragma unroll
                for (int sh = 8; sh > 0; sh >>= 1) s += __shfl_xor_sync(0xFFFFFFFFu, s, sh);
                if (sub == 0) {
                    float dd = (s > 0.f) ? sqrtf(s) : 0.f;
                    g_d[i * N_ + j] = dd;
                    // d>2 => every RBF term exp(<-127) == exactly 0.0f in fp32 (same as ref)
                    bool act = (dd <= 2.0f);
                    g_act[i * N_ + j] = act ? 1 : 0;
                    if (act) {
                        int p = atomicAdd(&g_pairCount, 1);
                        g_pairList[p] = i * N_ + j;
                    }
                }
            }
        }
        {
            int c = t & 63, part = t >> 6;
            float acc = 0.f;
            const float* wp = embW + (part * 64) * D_ + c;
#pragma unroll 16
            for (int f = 0; f < 64; f++) acc += sx[part * 64 + f] * wp[f * D_];
            red[t] = acc;
        }
        __syncthreads();
        if (t < D_) {
            float v = red[t] + red[t + 64] + red[t + 128] + red[t + 192] + embB[t];
            g_q[i * D_ + t] = v;
            g_k[i * D_ + t] = v;
        }
        float pacc = sx[t] * boutW[t];
#pragma unroll
        for (int s = 16; s > 0; s >>= 1) pacc += __shfl_xor_sync(0xFFFFFFFFu, pacc, s);
        if ((t & 31) == 0) wred[t >> 5] = pacc;
        __syncthreads();
        if (t == 0) {
            float s = 0.f;
#pragma unroll
            for (int w = 0; w < 8; w++) s += wred[w];
            g_pred0[i] = s + boutB[0];
        }
    } else {
        int bt = b - 128;
        int c = tid & 63, rg = tid >> 6;
        if (bt < 16) {
            // ---- Atilde (l,h) + col-bias b~ ----
            int l = bt >> 2, h = bt & 3;
            float (*smK)[65] = (float(*)[65])sm;
            float acc[8];
#pragma unroll
            for (int u = 0; u < 8; u++) acc[u] = 0.f;
            float bacc = 0.f;
            for (int d0 = 0; d0 < DH_; d0 += 64) {
                __syncthreads();
                for (int idx = tid; idx < 4096; idx += 512) {
                    int cc = idx >> 6, d = idx & 63;
                    smK[cc][d] = kpW[l * (D_ * HD_) + cc * HD_ + h * DH_ + d0 + d];
                }
                __syncthreads();
                const float* qp = qpW + l * (D_ * HD_) + h * DH_ + d0;
                const float* qb = qpB + l * HD_ + h * DH_ + d0;
#pragma unroll 4
                for (int d = 0; d < 64; d++) {
                    float w = smK[c][d];
#pragma unroll
                    for (int u = 0; u < 8; u++) acc[u] += qp[(rg * 8 + u) * HD_ + d] * w;
                    if (rg == 0) bacc += w * qb[d];
                }
            }
            const float s = 0.08838834764831843f;  // 1/sqrt(128)
#pragma unroll
            for (int u = 0; u < 8; u++)
                g_At[((l * H_ + h) * D_ + rg * 8 + u) * D_ + c] = acc[u] * s;
            if (rg == 0) g_bt[(l * H_ + h) * D_ + c] = bacc * s;
        } else if (bt < 24) {
            // ---- M (l,qk) + v ----
            int l = (bt - 16) >> 1, qk = (bt - 16) & 1;
            const float* Wp  = (qk ? kpW : qpW) + l * D_ * HD_;
            const float* WpB = (qk ? kpB : qpB) + l * HD_;
            const float* Wo  = (qk ? koW : qoW) + l * HD_ * D_;
            const float* WoB = (qk ? koB : qoB) + l * D_;
            float (*smP)[65] = (float(*)[65])sm;
            float acc[8];
#pragma unroll
            for (int u = 0; u < 8; u++) acc[u] = 0.f;
            float vacc = 0.f;
            for (int s0 = 0; s0 < HD_; s0 += 64) {
                __syncthreads();
                for (int idx = tid; idx < 4096; idx += 512) {
                    int dd = idx >> 6, ss = idx & 63;
                    smP[dd][ss] = Wp[dd * HD_ + s0 + ss];
                }
                __syncthreads();
#pragma unroll 4
                for (int ss = 0; ss < 64; ss++) {
                    int s = s0 + ss;
                    int m = ((s & 127) << 2) | (s >> 7);   // inverse head/dh permutation
                    float w = Wo[m * D_ + c];
#pragma unroll
                    for (int u = 0; u < 8; u++) acc[u] += smP[rg * 8 + u][ss] * w;
                    if (rg == 0) vacc += WpB[s] * w;
                }
            }
#pragma unroll
            for (int u = 0; u < 8; u++)
                g_M[((l * 2 + qk) * D_ + rg * 8 + u) * D_ + c] = acc[u];
            if (rg == 0) g_v[(l * 2 + qk) * D_ + c] = vacc + WoB[c];
        } else {
            // ---- transpose bpW (4) + bowW (3) for vectorized P1 GEMVs ----
            int w = bt - 24;                   // 0..39
            for (int e = w * 512 + tid; e < 7 * 65536; e += 40 * 512) {
                int m = e >> 16, r = e & 65535;
                if (m < 4) {
                    int cc = r >> 9, col = r & 511;          // read coalesced over col
                    g_bpWT[m * 65536 + col * 128 + cc] = bpW[m * 65536 + cc * 512 + col];
                } else {
                    int l = m - 4, o = r >> 7, cc = r & 127; // read coalesced over cc
                    g_bowWT[l * 65536 + cc * 512 + o] = bowW[l * 65536 + o * 128 + cc];
                }
            }
        }
    }
    gridBar();

    // ===== Phase 1: blocks 0-127: bias pipeline (vectorized) ; 128-191: A-chain =====
    if (b < 128) {
        float (*beta)[BD_]  = (float(*)[BD_])sm;                 // 2 KB
        float (*sb)[HBD_]   = (float(*)[HBD_])(sm + 2048);       // 8 KB
        float (*parts)[512] = (float(*)[512])(sm + 10240);       // 8 KB
        int*   svp          = (int*)(sm + 18432);
        float* sd           = (float*)(sm + 18464);
        int total = g_pairCount + 1;
        int nChunks = (total + 3) >> 2;
        for (int ch = b; ch < nChunks; ch += 128) {
            int pbase = ch << 2;
            int np = total - pbase; if (np > 4) np = 4;
            if (tid < 4) {
                int vp = pbase + tid;
                if (tid < np) {
                    if (vp == 0) { svp[tid] = -1; sd[tid] = 0.f; }
                    else { int pr = g_pairList[vp - 1]; svp[tid] = pr; sd[tid] = g_d[pr]; }
                } else { svp[tid] = -2; sd[tid] = 0.f; }
            }
            __syncthreads();
            {
                int p = tid >> 7, c = tid & 127;
                float ddv = sd[p] - (float)c * (1.0f / 127.0f);
                beta[p][c] = (p < np && svp[p] >= 0) ? expf(-127.0f * ddv * ddv) : 0.f;
            }
            __syncthreads();
            for (int l = 0; l < L_; l++) {
                // GEMV1 (vectorized): out col = tid, 4 pairs
                const float4* WT = (const float4*)(g_bpWT + l * 65536) + tid * 32;
                const float4* b0p = (const float4*)beta[0];
                const float4* b1p = (const float4*)beta[1];
                const float4* b2p = (const float4*)beta[2];
                const float4* b3p = (const float4*)beta[3];
                float acc0 = 0.f, acc1 = 0.f, acc2 = 0.f, acc3 = 0.f;
#pragma unroll 8
                for (int c4 = 0; c4 < 32; c4++) {
                    float4 w = WT[c4];
                    float4 x0 = b0p[c4], x1 = b1p[c4], x2 = b2p[c4], x3 = b3p[c4];
                    acc0 += w.x * x0.x + w.y * x0.y + w.z * x0.z + w.w * x0.w;
                    acc1 += w.x * x1.x + w.y * x1.y + w.z * x1.z + w.w * x1.w;
                    acc2 += w.x * x2.x + w.y * x2.y + w.z * x2.z + w.w * x2.w;
                    acc3 += w.x * x3.x + w.y * x3.y + w.z * x3.z + w.w * x3.w;
                }
                float bb = bpB[l * HBD_ + tid];
                sb[0][tid] = acc0 + bb;
                sb[1][tid] = acc1 + bb;
                sb[2][tid] = acc2 + bb;
                sb[3][tid] = acc3 + bb;
                __syncthreads();
                if (tid < 16) {
                    int p = tid >> 2, h = tid & 3;
                    if (p < np && svp[p] != -2) {
                        const float4* sp4 = (const float4*)(sb[p] + h * BD_);
                        float s = 0.f;
#pragma unroll 8
                        for (int k = 0; k < 32; k++) {
                            float4 v = sp4[k];
                            s += v.x * v.x + v.y * v.y + v.z * v.z + v.w * v.w;
                        }
                        float r = sqrtf(s);
                        if (svp[p] == -1) g_cdiffs[l * H_ + h] = r;
                        else              g_diffs[(l * H_ + h) * (N_ * N_) + svp[p]] = r;
                    }
                }
                if (l < L_ - 1) {
                    // GEMV2 (vectorized): out col c, o-range split over 4 groups
                    int c = tid & 127, os = tid >> 7;
                    const float4* WT2 = (const float4*)(g_bowWT + l * 65536)
                                        + c * 128 + os * 32;
                    const float4* s0p = (const float4*)sb[0] + os * 32;
                    const float4* s1p = (const float4*)sb[1] + os * 32;
                    const float4* s2p = (const float4*)sb[2] + os * 32;
                    const float4* s3p = (const float4*)sb[3] + os * 32;
                    float a0 = 0.f, a1 = 0.f, a2 = 0.f, a3 = 0.f;
#pragma unroll 8
                    for (int k = 0; k < 32; k++) {
                        float4 w = WT2[k];
                        float4 y0 = s0p[k], y1 = s1p[k], y2 = s2p[k], y3 = s3p[k];
                        a0 += w.x * y0.x + w.y * y0.y + w.z * y0.z + w.w * y0.w;
                        a1 += w.x * y1.x + w.y * y1.y + w.z * y1.z + w.w * y1.w;
                        a2 += w.x * y2.x + w.y * y2.y + w.z * y2.z + w.w * y2.w;
                        a3 += w.x * y3.x + w.y * y3.y + w.z * y3.z + w.w * y3.w;
                    }
                    parts[os][0 * BD_ + c] = a0;
                    parts[os][1 * BD_ + c] = a1;
                    parts[os][2 * BD_ + c] = a2;
                    parts[os][3 * BD_ + c] = a3;
                    __syncthreads();
                    int p = tid >> 7, cc = tid & 127;
                    float v = parts[0][p * BD_ + cc] + parts[1][p * BD_ + cc]
                            + parts[2][p * BD_ + cc] + parts[3][p * BD_ + cc]
                            + bowB[l * BD_ + cc];
                    beta[p][cc] = mishf(v);
                }
                __syncthreads();
            }
            __syncthreads();
        }
    } else {
        // -------- A-chain: 8 rows per block, all 4 layers, row-local --------
        float (*sq)[D_]  = (float(*)[D_])sm;
        float (*srs)[D_] = (float(*)[D_])(sm + 2048);
        float (*srq)[D_] = (float(*)[D_])(sm + 4096);
        int ab = b - 128; bool isK = ab >= 32; int r0 = (ab & 31) * 8;
        int rr = tid >> 6, c = tid & 63, row = r0 + rr;
        sq[rr][c] = (isK ? g_k : g_q)[row * D_ + c];
        __syncthreads();
        for (int l = 0; l < L_; l++) {
            float au = 0.f;
            if (!isK) {
                const float* A0 = g_At + ((l * H_ + 0) * D_) * D_;
                const float* A1 = g_At + ((l * H_ + 1) * D_) * D_;
                const float* A2 = g_At + ((l * H_ + 2) * D_) * D_;
                const float* A3 = g_At + ((l * H_ + 3) * D_) * D_;
                const float* Mq = g_M + (l * 2 + 0) * D_ * D_;
                float b0 = 0, b1 = 0, b2 = 0, b3 = 0;
#pragma unroll 8
                for (int d = 0; d < D_; d++) {
                    float qv = sq[rr][d];
                    b0 += qv * A0[d * D_ + c];
                    b1 += qv * A1[d * D_ + c];
                    b2 += qv * A2[d * D_ + c];
                    b3 += qv * A3[d * D_ + c];
                    au += qv * Mq[d * D_ + c];
                }
                g_B[((l * H_ + 0) * N_ + row) * D_ + c] = b0;
                g_B[((l * H_ + 1) * N_ + row) * D_ + c] = b1;
                g_B[((l * H_ + 2) * N_ + row) * D_ + c] = b2;
                g_B[((l * H_ + 3) * N_ + row) * D_ + c] = b3;
                au += g_v[(l * 2 + 0) * D_ + c];
            } else {
                const float* Mk = g_M + (l * 2 + 1) * D_ * D_;
#pragma unroll 8
                for (int d = 0; d < D_; d++) au += sq[rr][d] * Mk[d * D_ + c];
                au += g_v[(l * 2 + 1) * D_ + c];
                ((float*)g_kT4)[((l * 16 + (c >> 2)) * N_ + row) * 4 + (c & 3)] = sq[rr][c];
                if (c < 4) {
                    const float* bt = g_bt + (l * H_ + c) * D_;
                    float s = 0.f;
#pragma unroll 8
                    for (int d = 0; d < D_; d++) s += sq[rr][d] * bt[d];
                    g_colK[(l * H_ + c) * N_ + row] = s;
                }
            }
            if (l < L_ - 1) {
                float y = sq[rr][c] + mishf(au);
                srs[rr][c] = y; srq[rr][c] = y * y;
                __syncthreads();
                for (int s = 32; s > 0; s >>= 1) {
                    if (c < s) { srs[rr][c] += srs[rr][c + s]; srq[rr][c] += srq[rr][c + s]; }
                    __syncthreads();
                }
                const float* G  = (isK ? klnG : qlnG) + l * D_;
                const float* Bt = (isK ? klnB : qlnB) + l * D_;
                float mean = srs[rr][0] * (1.0f / 64.0f);
                float var  = srq[rr][0] * (1.0f / 64.0f) - mean * mean;
                float o = (y - mean) * rsqrtf(var + EPS_) * G[c] + Bt[c];
                __syncthreads();
                sq[rr][c] = o;
                __syncthreads();
            }
        }
    }
    gridBar();

    // ====== Phase 2: 512 (l,h,tile8) softmax units, fully parallel, grid-stride =====
    {
        float (*sB)[D_]   = (float(*)[D_])sm;                     // 2 KB
        float4 (*sB4)[16] = (float4(*)[16])sm;
        float (*parts)[8][256] = (float(*)[8][256])(sm + 2048);   // 16 KB
        for (int u = b; u < 512; u += G_) {
            int l = u >> 7, h = (u >> 5) & 3, i0 = (u & 31) * 8;
            __syncthreads();
            sB[tid >> 6][tid & 63] =
                g_B[((l * H_ + h) * N_ + i0 + (tid >> 6)) * D_ + (tid & 63)];
            __syncthreads();
            int half = tid >> 8, j = tid & 255;
            float acc[8];
#pragma unroll
            for (int ii = 0; ii < 8; ii++) acc[ii] = 0.f;
            const float4* kt = g_kT4 + (l * 16 + half * 8) * N_ + j;
#pragma unroll
            for (int d4 = 0; d4 < 8; d4++) {
                float4 kv = kt[d4 * N_];
#pragma unroll
                for (int ii = 0; ii < 8; ii++) {
                    float4 q = sB4[ii][half * 8 + d4];
                    acc[ii] += q.x * kv.x + q.y * kv.y + q.z * kv.z + q.w * kv.w;
                }
            }
#pragma unroll
            for (int ii = 0; ii < 8; ii++) parts[half][ii][j] = acc[ii];
            __syncthreads();
            if (tid < 256) {
                float ck = g_colK[(l * H_ + h) * N_ + j];
                float cd = g_cdiffs[l * H_ + h];
                const float* dptr = g_diffs + (l * H_ + h) * (N_ * N_);
#pragma unroll
                for (int ii = 0; ii < 8; ii++) {
                    int pr = (i0 + ii) * N_ + j;
                    float dv = g_act[pr] ? dptr[pr] : cd;
                    parts[0][ii][j] = parts[0][ii][j] + parts[1][ii][j] + ck + dv;
                }
            }
            __syncthreads();
            int w = tid >> 5, lane = tid & 31;
            if (w < 8) {                          // warp w owns row i0+w
                int i = i0 + w;
                float a[8];
#pragma unroll
                for (int k = 0; k < 8; k++) a[k] = parts[0][w][k * 32 + lane];
                float mx = a[0];
#pragma unroll
                for (int k = 1; k < 8; k++) mx = fmaxf(mx, a[k]);
#pragma unroll
                for (int s = 16; s > 0; s >>= 1) mx = fmaxf(mx, __shfl_xor_sync(0xFFFFFFFFu, mx, s));
                float e[8], ssum = 0.f, vs = 0.f, eD = 0.f;
#pragma unroll
                for (int k = 0; k < 8; k++) {
                    e[k] = expf(a[k] - mx);
                    ssum += e[k];
                    int jj = k * 32 + lane;
                    vs += e[k] * nt[jj];
                    if (jj == i) eD = e[k];
                }
#pragma unroll
                for (int s = 16; s > 0; s >>= 1) {
                    ssum += __shfl_xor_sync(0xFFFFFFFFu, ssum, s);
                    vs   += __shfl_xor_sync(0xFFFFFFFFu, vs, s);
                    eD   += __shfl_xor_sync(0xFFFFFFFFu, eD, s);
                }
                if (lane == 0) {
                    float inv = 1.0f / ssum;
                    g_base[(l * H_ + h) * N_ + i] = (vs - eD * nt[i]) * inv;
                    g_w[(l * H_ + h) * N_ + i]    = eD * inv;
                }
            }
        }
    }
    gridBar();

    // ====== Phase 3: scalar affine fold over layers -> out ======
    if (b == 0) {
        if (tid < 256) {
            int i = tid;
            float p = g_pred0[i];
#pragma unroll
            for (int l = 0; l < L_; l++) {
                float s = 0.f;
#pragma unroll
                for (int h = 0; h < H_; h++)
                    s += g_base[(l * H_ + h) * N_ + i] + g_w[(l * H_ + h) * N_ + i] * p;
                p = 0.25f * s;
            }
            out[i] = p;
        }
        if (tid == 256) g_pairCount = 0;   // prep next replay
    }
}

// ---------------- launch ----------------
extern "C" void kernel_launch(void* const* d_in, const int* in_sizes, int n_in,
                              void* d_out, int out_size) {
    const float* X     = (const float*)d_in[0];
    const float* E     = (const float*)d_in[1];
    const float* nt    = (const float*)d_in[2];
    const float* embW  = (const float*)d_in[3];
    const float* embB  = (const float*)d_in[4];
    const float* boutW = (const float*)d_in[5];
    const float* boutB = (const float*)d_in[6];
    const float* qpW   = (const float*)d_in[7];
    const float* qpB   = (const float*)d_in[8];
    const float* kpW   = (const float*)d_in[9];
    const float* kpB   = (const float*)d_in[10];
    const float* qoW   = (const float*)d_in[11];
    const float* qoB   = (const float*)d_in[12];
    const float* koW   = (const float*)d_in[13];
    const float* koB   = (const float*)d_in[14];
    const float* bpW   = (const float*)d_in[15];
    const float* bpB   = (const float*)d_in[16];
    const float* bowW  = (const float*)d_in[17];
    const float* bowB  = (const float*)d_in[18];
    const float* qlnG  = (const float*)d_in[19];
    const float* qlnB  = (const float*)d_in[20];
    const float* klnG  = (const float*)d_in[21];
    const float* klnB  = (const float*)d_in[22];
    float* out = (float*)d_out;

    k_mega<<<G_, 512>>>(X, E, nt, embW, embB, boutW, boutB,
                        qpW, qpB, kpW, kpB, qoW, qoB, koW, koB,
                        bpW, bpB, bowW, bowB, qlnG, qlnB, klnG, klnB, out);
}

// round 15
// speedup vs baseline: 1.3803x; 1.3803x over previous
#include <cuda_runtime.h>
#include <math.h>

#define N_   256
#define FB_  256
#define D_   64
#define H_   4
#define DH_  128
#define HD_  512
#define BD_  128
#define HBD_ 512
#define AK_  100
#define L_   4
#define EPS_ 1e-5f
#define G_   192   // persistent grid; all blocks co-resident (2/SM guaranteed)

// ---------------- scratch (device globals; zero-init, no allocations) ----------------
__device__ float g_d[N_ * N_];
__device__ unsigned char g_act[N_ * N_];
__device__ int   g_pairCount;
__device__ int   g_pairList[N_ * N_];
__device__ float g_diffs[L_ * H_ * N_ * N_];
__device__ float g_cdiffs[L_ * H_];
__device__ float g_q[N_ * D_];
__device__ float g_k[N_ * D_];
__device__ float g_pred0[N_];
__device__ float g_At[L_ * H_ * D_ * D_];      // [l][h][d][c] = Wq_h Wk_h^T / sqrt(DH)
__device__ float g_M[L_ * 2 * D_ * D_];        // [l][qk][d][c] effective update matrix
__device__ float g_v[L_ * 2 * D_];             // effective update bias
__device__ float g_bt[L_ * H_ * D_];           // [l][h][c]
__device__ float g_B[L_ * H_ * N_ * D_];       // [l][h][i][c]
__device__ float4 g_kT4[L_ * 16 * N_];         // [l][d4][j]
__device__ float g_colK[L_ * H_ * N_];         // [l][h][j]
__device__ float g_base[L_ * H_ * N_];         // attention affine constants
__device__ float g_w[L_ * H_ * N_];
__device__ unsigned g_barArrive;
__device__ unsigned g_barGen;

__device__ __forceinline__ float mishf(float x) {
    float sp = (x > 20.f) ? x : log1pf(expf(x));
    return x * tanhf(sp);
}

__device__ __forceinline__ void gridBar() {
    __threadfence();
    __syncthreads();
    if (threadIdx.x == 0) {
        unsigned gen = __ldcg(&g_barGen);
        unsigned t = atomicAdd(&g_barArrive, 1u);
        if (t == G_ - 1) {
            g_barArrive = 0u;
            __threadfence();
            atomicExch(&g_barGen, gen + 1u);
        } else {
            while (__ldcg(&g_barGen) == gen) __nanosleep(32);
        }
    }
    __syncthreads();
    __threadfence();
}

__global__ __launch_bounds__(512, 2)
void k_mega(const float* __restrict__ X, const float* __restrict__ E,
            const float* __restrict__ nt,
            const float* __restrict__ embW, const float* __restrict__ embB,
            const float* __restrict__ boutW, const float* __restrict__ boutB,
            const float* __restrict__ qpW, const float* __restrict__ qpB,
            const float* __restrict__ kpW, const float* __restrict__ kpB,
            const float* __restrict__ qoW, const float* __restrict__ qoB,
            const float* __restrict__ koW, const float* __restrict__ koB,
            const float* __restrict__ bpW, const float* __restrict__ bpB,
            const float* __restrict__ bowW, const float* __restrict__ bowB,
            const float* __restrict__ qlnG, const float* __restrict__ qlnB,
            const float* __restrict__ klnG, const float* __restrict__ klnB,
            float* __restrict__ out) {
    __shared__ __align__(16) char sm[20608];
    int b = blockIdx.x, tid = threadIdx.x;     // 512 threads

    // ============ Phase 0: blocks 0-127: embed/pred0/dist ; 128-191: PRE ============
    if (b < 128) {
        int half = tid >> 8, t = tid & 255;
        char* hb = sm + half * 2560;
        float* sx   = (float*)hb;
        float* se   = (float*)(hb + 1024);
        float* red  = (float*)(hb + 1440);
        float* wred = (float*)(hb + 2464);
        int i = 2 * b + half;
        sx[t] = X[i * FB_ + t];
        if (t < AK_) se[t] = E[i * AK_ + t];
        __syncthreads();
        // ---- distances: warp-cooperative, 16 lanes per j row (coalesced E reads) ----
        {
            int w8 = (t >> 5);
            int lane = t & 31;
            int sub = lane & 15, jh = lane >> 4;
            for (int pass = 0; pass < 16; pass++) {
                int j = pass * 16 + w8 * 2 + jh;
                float s = 0.f;
                const float* Ej = E + j * AK_;
#pragma unroll
                for (int k = sub; k < AK_; k += 16) { float d = se[k] - Ej[k]; s += d * d; }
#pragma unroll
                for (int sh = 8; sh > 0; sh >>= 1) s += __shfl_xor_sync(0xFFFFFFFFu, s, sh);
                if (sub == 0) {
                    float dd = (s > 0.f) ? sqrtf(s) : 0.f;
                    g_d[i * N_ + j] = dd;
                    // d>2 => every RBF term exp(<-127) == exactly 0.0f in fp32 (same as ref)
                    bool act = (dd <= 2.0f);
                    g_act[i * N_ + j] = act ? 1 : 0;
                    if (act) {
                        int p = atomicAdd(&g_pairCount, 1);
                        g_pairList[p] = i * N_ + j;
                    }
                }
            }
        }
        {
            int c = t & 63, part = t >> 6;
            float acc = 0.f;
            const float* wp = embW + (part * 64) * D_ + c;
#pragma unroll 16
            for (int f = 0; f < 64; f++) acc += sx[part * 64 + f] * wp[f * D_];
            red[t] = acc;
        }
        __syncthreads();
        if (t < D_) {
            float v = red[t] + red[t + 64] + red[t + 128] + red[t + 192] + embB[t];
            g_q[i * D_ + t] = v;
            g_k[i * D_ + t] = v;
        }
        float pacc = sx[t] * boutW[t];
#pragma unroll
        for (int s = 16; s > 0; s >>= 1) pacc += __shfl_xor_sync(0xFFFFFFFFu, pacc, s);
        if ((t & 31) == 0) wred[t >> 5] = pacc;
        __syncthreads();
        if (t == 0) {
            float s = 0.f;
#pragma unroll
            for (int w = 0; w < 8; w++) s += wred[w];
            g_pred0[i] = s + boutB[0];
        }
    } else {
        int bt = b - 128;
        int c = tid & 63, rg = tid >> 6;
        if (bt < 16) {
            // ---- Atilde (l,h) + col-bias b~ ----
            int l = bt >> 2, h = bt & 3;
            float (*smK)[65] = (float(*)[65])sm;
            float acc[8];
#pragma unroll
            for (int u = 0; u < 8; u++) acc[u] = 0.f;
            float bacc = 0.f;
            for (int d0 = 0; d0 < DH_; d0 += 64) {
                __syncthreads();
                for (int idx = tid; idx < 4096; idx += 512) {
                    int cc = idx >> 6, d = idx & 63;
                    smK[cc][d] = kpW[l * (D_ * HD_) + cc * HD_ + h * DH_ + d0 + d];
                }
                __syncthreads();
                const float* qp = qpW + l * (D_ * HD_) + h * DH_ + d0;
                const float* qb = qpB + l * HD_ + h * DH_ + d0;
#pragma unroll 4
                for (int d = 0; d < 64; d++) {
                    float w = smK[c][d];
#pragma unroll
                    for (int u = 0; u < 8; u++) acc[u] += qp[(rg * 8 + u) * HD_ + d] * w;
                    if (rg == 0) bacc += w * qb[d];
                }
            }
            const float s = 0.08838834764831843f;  // 1/sqrt(128)
#pragma unroll
            for (int u = 0; u < 8; u++)
                g_At[((l * H_ + h) * D_ + rg * 8 + u) * D_ + c] = acc[u] * s;
            if (rg == 0) g_bt[(l * H_ + h) * D_ + c] = bacc * s;
        } else if (bt < 24) {
            // ---- M (l,qk) + v ----
            int l = (bt - 16) >> 1, qk = (bt - 16) & 1;
            const float* Wp  = (qk ? kpW : qpW) + l * D_ * HD_;
            const float* WpB = (qk ? kpB : qpB) + l * HD_;
            const float* Wo  = (qk ? koW : qoW) + l * HD_ * D_;
            const float* WoB = (qk ? koB : qoB) + l * D_;
            float (*smP)[65] = (float(*)[65])sm;
            float acc[8];
#pragma unroll
            for (int u = 0; u < 8; u++) acc[u] = 0.f;
            float vacc = 0.f;
            for (int s0 = 0; s0 < HD_; s0 += 64) {
                __syncthreads();
                for (int idx = tid; idx < 4096; idx += 512) {
                    int dd = idx >> 6, ss = idx & 63;
                    smP[dd][ss] = Wp[dd * HD_ + s0 + ss];
                }
                __syncthreads();
#pragma unroll 4
                for (int ss = 0; ss < 64; ss++) {
                    int s = s0 + ss;
                    int m = ((s & 127) << 2) | (s >> 7);   // inverse head/dh permutation
                    float w = Wo[m * D_ + c];
#pragma unroll
                    for (int u = 0; u < 8; u++) acc[u] += smP[rg * 8 + u][ss] * w;
                    if (rg == 0) vacc += WpB[s] * w;
                }
            }
#pragma unroll
            for (int u = 0; u < 8; u++)
                g_M[((l * 2 + qk) * D_ + rg * 8 + u) * D_ + c] = acc[u];
            if (rg == 0) g_v[(l * 2 + qk) * D_ + c] = vacc + WoB[c];
        }
    }
    gridBar();

    // ===== Phase 1: blocks 0-127: bias pipeline ; 128-191: full 4-layer A-chain =====
    if (b < 128) {
        float (*beta)[BD_]  = (float(*)[BD_])sm;                 // 2 KB
        float (*sb)[HBD_]   = (float(*)[HBD_])(sm + 2048);       // 8 KB
        float (*parts)[512] = (float(*)[512])(sm + 10240);       // 8 KB
        int*   svp          = (int*)(sm + 18432);
        float* sd           = (float*)(sm + 18464);
        int total = g_pairCount + 1;
        int nChunks = (total + 3) >> 2;
        for (int ch = b; ch < nChunks; ch += 128) {
            int pbase = ch << 2;
            int np = total - pbase; if (np > 4) np = 4;
            if (tid < 4) {
                int vp = pbase + tid;
                if (tid < np) {
                    if (vp == 0) { svp[tid] = -1; sd[tid] = 0.f; }
                    else { int pr = g_pairList[vp - 1]; svp[tid] = pr; sd[tid] = g_d[pr]; }
                } else { svp[tid] = -2; sd[tid] = 0.f; }
            }
            __syncthreads();
            {
                int p = tid >> 7, c = tid & 127;
                float ddv = sd[p] - (float)c * (1.0f / 127.0f);
                beta[p][c] = (p < np && svp[p] >= 0) ? expf(-127.0f * ddv * ddv) : 0.f;
            }
            __syncthreads();
            for (int l = 0; l < L_; l++) {
                // GEMV1: coalesced weight loads, float4 smem operand, 4 c per iter
                const float* W = bpW + l * BD_ * HBD_;
                const float4* b0p = (const float4*)beta[0];
                const float4* b1p = (const float4*)beta[1];
                const float4* b2p = (const float4*)beta[2];
                const float4* b3p = (const float4*)beta[3];
                float acc0 = 0.f, acc1 = 0.f, acc2 = 0.f, acc3 = 0.f;
#pragma unroll 8
                for (int c4 = 0; c4 < 32; c4++) {
                    const float* wb = W + (4 * c4) * HBD_ + tid;
                    float w0 = wb[0], w1 = wb[HBD_], w2 = wb[2 * HBD_], w3 = wb[3 * HBD_];
                    float4 x0 = b0p[c4], x1 = b1p[c4], x2 = b2p[c4], x3 = b3p[c4];
                    acc0 += w0 * x0.x + w1 * x0.y + w2 * x0.z + w3 * x0.w;
                    acc1 += w0 * x1.x + w1 * x1.y + w2 * x1.z + w3 * x1.w;
                    acc2 += w0 * x2.x + w1 * x2.y + w2 * x2.z + w3 * x2.w;
                    acc3 += w0 * x3.x + w1 * x3.y + w2 * x3.z + w3 * x3.w;
                }
                float bb = bpB[l * HBD_ + tid];
                sb[0][tid] = acc0 + bb;
                sb[1][tid] = acc1 + bb;
                sb[2][tid] = acc2 + bb;
                sb[3][tid] = acc3 + bb;
                __syncthreads();
                if (tid < 16) {
                    int p = tid >> 2, h = tid & 3;
                    if (p < np && svp[p] != -2) {
                        const float4* sp4 = (const float4*)(sb[p] + h * BD_);
                        float s = 0.f;
#pragma unroll 8
                        for (int k = 0; k < 32; k++) {
                            float4 v = sp4[k];
                            s += v.x * v.x + v.y * v.y + v.z * v.z + v.w * v.w;
                        }
                        float r = sqrtf(s);
                        if (svp[p] == -1) g_cdiffs[l * H_ + h] = r;
                        else              g_diffs[(l * H_ + h) * (N_ * N_) + svp[p]] = r;
                    }
                }
                if (l < L_ - 1) {
                    // GEMV2: coalesced weight loads, float4 broadcast smem, 4 o per iter
                    int c = tid & 127, os = tid >> 7;
                    const float* W2 = bowW + l * HBD_ * BD_ + c;
                    const float4* s0p = (const float4*)sb[0] + os * 32;
                    const float4* s1p = (const float4*)sb[1] + os * 32;
                    const float4* s2p = (const float4*)sb[2] + os * 32;
                    const float4* s3p = (const float4*)sb[3] + os * 32;
                    float a0 = 0.f, a1 = 0.f, a2 = 0.f, a3 = 0.f;
#pragma unroll 8
                    for (int k = 0; k < 32; k++) {
                        const float* wb = W2 + (os * 128 + 4 * k) * BD_;
                        float w0 = wb[0], w1 = wb[BD_], w2 = wb[2 * BD_], w3 = wb[3 * BD_];
                        float4 y0 = s0p[k], y1 = s1p[k], y2 = s2p[k], y3 = s3p[k];
                        a0 += w0 * y0.x + w1 * y0.y + w2 * y0.z + w3 * y0.w;
                        a1 += w0 * y1.x + w1 * y1.y + w2 * y1.z + w3 * y1.w;
                        a2 += w0 * y2.x + w1 * y2.y + w2 * y2.z + w3 * y2.w;
                        a3 += w0 * y3.x + w1 * y3.y + w2 * y3.z + w3 * y3.w;
                    }
                    parts[os][0 * BD_ + c] = a0;
                    parts[os][1 * BD_ + c] = a1;
                    parts[os][2 * BD_ + c] = a2;
                    parts[os][3 * BD_ + c] = a3;
                    __syncthreads();
                    int p = tid >> 7, cc = tid & 127;
                    float v = parts[0][p * BD_ + cc] + parts[1][p * BD_ + cc]
                            + parts[2][p * BD_ + cc] + parts[3][p * BD_ + cc]
                            + bowB[l * BD_ + cc];
                    beta[p][cc] = mishf(v);
                }
                __syncthreads();
            }
            __syncthreads();
        }
    } else {
        // -------- A-chain: 8 rows per block, all 4 layers, row-local --------
        float (*sq)[D_]  = (float(*)[D_])sm;
        float (*srs)[D_] = (float(*)[D_])(sm + 2048);
        float (*srq)[D_] = (float(*)[D_])(sm + 4096);
        int ab = b - 128; bool isK = ab >= 32; int r0 = (ab & 31) * 8;
        int rr = tid >> 6, c = tid & 63, row = r0 + rr;
        sq[rr][c] = (isK ? g_k : g_q)[row * D_ + c];
        __syncthreads();
        for (int l = 0; l < L_; l++) {
            float au = 0.f;
            if (!isK) {
                const float* A0 = g_At + ((l * H_ + 0) * D_) * D_;
                const float* A1 = g_At + ((l * H_ + 1) * D_) * D_;
                const float* A2 = g_At + ((l * H_ + 2) * D_) * D_;
                const float* A3 = g_At + ((l * H_ + 3) * D_) * D_;
                const float* Mq = g_M + (l * 2 + 0) * D_ * D_;
                float b0 = 0, b1 = 0, b2 = 0, b3 = 0;
#pragma unroll 8
                for (int d = 0; d < D_; d++) {
                    float qv = sq[rr][d];
                    b0 += qv * A0[d * D_ + c];
                    b1 += qv * A1[d * D_ + c];
                    b2 += qv * A2[d * D_ + c];
                    b3 += qv * A3[d * D_ + c];
                    au += qv * Mq[d * D_ + c];
                }
                g_B[((l * H_ + 0) * N_ + row) * D_ + c] = b0;
                g_B[((l * H_ + 1) * N_ + row) * D_ + c] = b1;
                g_B[((l * H_ + 2) * N_ + row) * D_ + c] = b2;
                g_B[((l * H_ + 3) * N_ + row) * D_ + c] = b3;
                au += g_v[(l * 2 + 0) * D_ + c];
            } else {
                const float* Mk = g_M + (l * 2 + 1) * D_ * D_;
#pragma unroll 8
                for (int d = 0; d < D_; d++) au += sq[rr][d] * Mk[d * D_ + c];
                au += g_v[(l * 2 + 1) * D_ + c];
                ((float*)g_kT4)[((l * 16 + (c >> 2)) * N_ + row) * 4 + (c & 3)] = sq[rr][c];
                if (c < 4) {
                    const float* bt = g_bt + (l * H_ + c) * D_;
                    float s = 0.f;
#pragma unroll 8
                    for (int d = 0; d < D_; d++) s += sq[rr][d] * bt[d];
                    g_colK[(l * H_ + c) * N_ + row] = s;
                }
            }
            if (l < L_ - 1) {
                float y = sq[rr][c] + mishf(au);
                srs[rr][c] = y; srq[rr][c] = y * y;
                __syncthreads();
                for (int s = 32; s > 0; s >>= 1) {
                    if (c < s) { srs[rr][c] += srs[rr][c + s]; srq[rr][c] += srq[rr][c + s]; }
                    __syncthreads();
                }
                const float* G  = (isK ? klnG : qlnG) + l * D_;
                const float* Bt = (isK ? klnB : qlnB) + l * D_;
                float mean = srs[rr][0] * (1.0f / 64.0f);
                float var  = srq[rr][0] * (1.0f / 64.0f) - mean * mean;
                float o = (y - mean) * rsqrtf(var + EPS_) * G[c] + Bt[c];
                __syncthreads();
                sq[rr][c] = o;
                __syncthreads();
            }
        }
    }
    gridBar();

    // ====== Phase 2: 512 (l,h,tile8) softmax units, fully parallel, grid-stride =====
    {
        float (*sB)[D_]   = (float(*)[D_])sm;                     // 2 KB
        float4 (*sB4)[16] = (float4(*)[16])sm;
        float (*parts)[8][256] = (float(*)[8][256])(sm + 2048);   // 16 KB
        for (int u = b; u < 512; u += G_) {
            int l = u >> 7, h = (u >> 5) & 3, i0 = (u & 31) * 8;
            __syncthreads();
            sB[tid >> 6][tid & 63] =
                g_B[((l * H_ + h) * N_ + i0 + (tid >> 6)) * D_ + (tid & 63)];
            __syncthreads();
            int half = tid >> 8, j = tid & 255;
            float acc[8];
#pragma unroll
            for (int ii = 0; ii < 8; ii++) acc[ii] = 0.f;
            const float4* kt = g_kT4 + (l * 16 + half * 8) * N_ + j;
#pragma unroll
            for (int d4 = 0; d4 < 8; d4++) {
                float4 kv = kt[d4 * N_];
#pragma unroll
                for (int ii = 0; ii < 8; ii++) {
                    float4 q = sB4[ii][half * 8 + d4];
                    acc[ii] += q.x * kv.x + q.y * kv.y + q.z * kv.z + q.w * kv.w;
                }
            }
#pragma unroll
            for (int ii = 0; ii < 8; ii++) parts[half][ii][j] = acc[ii];
            __syncthreads();
            if (tid < 256) {
                float ck = g_colK[(l * H_ + h) * N_ + j];
                float cd = g_cdiffs[l * H_ + h];
                const float* dptr = g_diffs + (l * H_ + h) * (N_ * N_);
#pragma unroll
                for (int ii = 0; ii < 8; ii++) {
                    int pr = (i0 + ii) * N_ + j;
                    float dv = g_act[pr] ? dptr[pr] : cd;
                    parts[0][ii][j] = parts[0][ii][j] + parts[1][ii][j] + ck + dv;
                }
            }
            __syncthreads();
            int w = tid >> 5, lane = tid & 31;
            if (w < 8) {                          // warp w owns row i0+w
                int i = i0 + w;
                float a[8];
#pragma unroll
                for (int k = 0; k < 8; k++) a[k] = parts[0][w][k * 32 + lane];
                float mx = a[0];
#pragma unroll
                for (int k = 1; k < 8; k++) mx = fmaxf(mx, a[k]);
#pragma unroll
                for (int s = 16; s > 0; s >>= 1) mx = fmaxf(mx, __shfl_xor_sync(0xFFFFFFFFu, mx, s));
                float e[8], ssum = 0.f, vs = 0.f, eD = 0.f;
#pragma unroll
                for (int k = 0; k < 8; k++) {
                    e[k] = expf(a[k] - mx);
                    ssum += e[k];
                    int jj = k * 32 + lane;
                    vs += e[k] * nt[jj];
                    if (jj == i) eD = e[k];
                }
#pragma unroll
                for (int s = 16; s > 0; s >>= 1) {
                    ssum += __shfl_xor_sync(0xFFFFFFFFu, ssum, s);
                    vs   += __shfl_xor_sync(0xFFFFFFFFu, vs, s);
                    eD   += __shfl_xor_sync(0xFFFFFFFFu, eD, s);
                }
                if (lane == 0) {
                    float inv = 1.0f / ssum;
                    g_base[(l * H_ + h) * N_ + i] = (vs - eD * nt[i]) * inv;
                    g_w[(l * H_ + h) * N_ + i]    = eD * inv;
                }
            }
        }
    }
    gridBar();

    // ====== Phase 3: scalar affine fold over layers -> out ======
    if (b == 0) {
        if (tid < 256) {
            int i = tid;
            float p = g_pred0[i];
#pragma unroll
            for (int l = 0; l < L_; l++) {
                float s = 0.f;
#pragma unroll
                for (int h = 0; h < H_; h++)
                    s += g_base[(l * H_ + h) * N_ + i] + g_w[(l * H_ + h) * N_ + i] * p;
                p = 0.25f * s;
            }
            out[i] = p;
        }
        if (tid == 256) g_pairCount = 0;   // prep next replay
    }
}

// ---------------- launch ----------------
extern "C" void kernel_launch(void* const* d_in, const int* in_sizes, int n_in,
                              void* d_out, int out_size) {
    const float* X     = (const float*)d_in[0];
    const float* E     = (const float*)d_in[1];
    const float* nt    = (const float*)d_in[2];
    const float* embW  = (const float*)d_in[3];
    const float* embB  = (const float*)d_in[4];
    const float* boutW = (const float*)d_in[5];
    const float* boutB = (const float*)d_in[6];
    const float* qpW   = (const float*)d_in[7];
    const float* qpB   = (const float*)d_in[8];
    const float* kpW   = (const float*)d_in[9];
    const float* kpB   = (const float*)d_in[10];
    const float* qoW   = (const float*)d_in[11];
    const float* qoB   = (const float*)d_in[12];
    const float* koW   = (const float*)d_in[13];
    const float* koB   = (const float*)d_in[14];
    const float* bpW   = (const float*)d_in[15];
    const float* bpB   = (const float*)d_in[16];
    const float* bowW  = (const float*)d_in[17];
    const float* bowB  = (const float*)d_in[18];
    const float* qlnG  = (const float*)d_in[19];
    const float* qlnB  = (const float*)d_in[20];
    const float* klnG  = (const float*)d_in[21];
    const float* klnB  = (const float*)d_in[22];
    float* out = (float*)d_out;

    k_mega<<<G_, 512>>>(X, E, nt, embW, embB, boutW, boutB,
                        qpW, qpB, kpW, kpB, qoW, qoB, koW, koB,
                        bpW, bpB, bowW, bowB, qlnG, qlnB, klnG, klnB, out);
}

// round 16
// speedup vs baseline: 1.5212x; 1.1021x over previous
#include <cuda_runtime.h>
#include <math.h>

#define N_   256
#define FB_  256
#define D_   64
#define H_   4
#define DH_  128
#define HD_  512
#define BD_  128
#define HBD_ 512
#define AK_  100
#define L_   4
#define EPS_ 1e-5f
#define G_   288   // persistent grid; 2/SM * 148 SMs = 296 capacity >= 288

// ---------------- scratch (device globals; zero-init, no allocations) ----------------
__device__ float g_d[N_ * N_];
__device__ unsigned char g_act[N_ * N_];
__device__ int   g_pairCount;
__device__ int   g_pairList[N_ * N_];
__device__ float g_diffs[L_ * H_ * N_ * N_];
__device__ float g_cdiffs[L_ * H_];
__device__ float g_q[N_ * D_];
__device__ float g_k[N_ * D_];
__device__ float g_pred0[N_];
__device__ float g_At[L_ * H_ * D_ * D_];      // [l][h][d][c] = Wq_h Wk_h^T / sqrt(DH)
__device__ float g_M[L_ * 2 * D_ * D_];        // [l][qk][d][c] effective update matrix
__device__ float g_v[L_ * 2 * D_];             // effective update bias
__device__ float g_bt[L_ * H_ * D_];           // [l][h][c]
__device__ float g_B[L_ * H_ * N_ * D_];       // [l][h][i][c]
__device__ float4 g_kT4[L_ * 16 * N_];         // [l][d4][j]
__device__ float g_colK[L_ * H_ * N_];         // [l][h][j]
__device__ float g_base[L_ * H_ * N_];         // attention affine constants
__device__ float g_w[L_ * H_ * N_];
__device__ unsigned g_barArrive;
__device__ unsigned g_barGen;

__device__ __forceinline__ float mishf(float x) {
    float sp = (x > 20.f) ? x : log1pf(expf(x));
    return x * tanhf(sp);
}

// Release-only grid barrier. Acquire fence dropped: L1 is no-write-allocate and
// every cross-phase address is first-loaded only after its producing barrier,
// so no stale L1 line can exist (audited per-buffer).
__device__ __forceinline__ void gridBar() {
    __threadfence();                           // release: order my stores before arrive
    __syncthreads();
    if (threadIdx.x == 0) {
        unsigned gen = __ldcg(&g_barGen);
        unsigned t = atomicAdd(&g_barArrive, 1u);
        if (t == G_ - 1) {
            g_barArrive = 0u;
            __threadfence();
            atomicExch(&g_barGen, gen + 1u);
        } else {
            while (__ldcg(&g_barGen) == gen) __nanosleep(32);
        }
    }
    __syncthreads();
}

__global__ __launch_bounds__(512, 2)
void k_mega(const float* __restrict__ X, const float* __restrict__ E,
            const float* __restrict__ nt,
            const float* __restrict__ embW, const float* __restrict__ embB,
            const float* __restrict__ boutW, const float* __restrict__ boutB,
            const float* __restrict__ qpW, const float* __restrict__ qpB,
            const float* __restrict__ kpW, const float* __restrict__ kpB,
            const float* __restrict__ qoW, const float* __restrict__ qoB,
            const float* __restrict__ koW, const float* __restrict__ koB,
            const float* __restrict__ bpW, const float* __restrict__ bpB,
            const float* __restrict__ bowW, const float* __restrict__ bowB,
            const float* __restrict__ qlnG, const float* __restrict__ qlnB,
            const float* __restrict__ klnG, const float* __restrict__ klnB,
            float* __restrict__ out) {
    __shared__ __align__(16) char sm[20608];
    int b = blockIdx.x, tid = threadIdx.x;     // 512 threads

    // ============ Phase 0: blocks 0-127: embed/pred0/dist ; 128-151: PRE ============
    if (b < 128) {
        int half = tid >> 8, t = tid & 255;
        char* hb = sm + half * 2560;
        float* sx   = (float*)hb;
        float* se   = (float*)(hb + 1024);
        float* red  = (float*)(hb + 1440);
        float* wred = (float*)(hb + 2464);
        int i = 2 * b + half;
        sx[t] = X[i * FB_ + t];
        if (t < AK_) se[t] = E[i * AK_ + t];
        __syncthreads();
        // ---- distances: warp-cooperative, 16 lanes per j row (coalesced E reads) ----
        {
            int w8 = (t >> 5);
            int lane = t & 31;
            int sub = lane & 15, jh = lane >> 4;
            for (int pass = 0; pass < 16; pass++) {
                int j = pass * 16 + w8 * 2 + jh;
                float s = 0.f;
                const float* Ej = E + j * AK_;
#pragma unroll
                for (int k = sub; k < AK_; k += 16) { float d = se[k] - Ej[k]; s += d * d; }
#pragma unroll
                for (int sh = 8; sh > 0; sh >>= 1) s += __shfl_xor_sync(0xFFFFFFFFu, s, sh);
                if (sub == 0) {
                    float dd = (s > 0.f) ? sqrtf(s) : 0.f;
                    g_d[i * N_ + j] = dd;
                    // d>2 => every RBF term exp(<-127) == exactly 0.0f in fp32 (same as ref)
                    bool act = (dd <= 2.0f);
                    g_act[i * N_ + j] = act ? 1 : 0;
                    if (act) {
                        int p = atomicAdd(&g_pairCount, 1);
                        g_pairList[p] = i * N_ + j;
                    }
                }
            }
        }
        {
            int c = t & 63, part = t >> 6;
            float acc = 0.f;
            const float* wp = embW + (part * 64) * D_ + c;
#pragma unroll 16
            for (int f = 0; f < 64; f++) acc += sx[part * 64 + f] * wp[f * D_];
            red[t] = acc;
        }
        __syncthreads();
        if (t < D_) {
            float v = red[t] + red[t + 64] + red[t + 128] + red[t + 192] + embB[t];
            g_q[i * D_ + t] = v;
            g_k[i * D_ + t] = v;
        }
        float pacc = sx[t] * boutW[t];
#pragma unroll
        for (int s = 16; s > 0; s >>= 1) pacc += __shfl_xor_sync(0xFFFFFFFFu, pacc, s);
        if ((t & 31) == 0) wred[t >> 5] = pacc;
        __syncthreads();
        if (t == 0) {
            float s = 0.f;
#pragma unroll
            for (int w = 0; w < 8; w++) s += wred[w];
            g_pred0[i] = s + boutB[0];
        }
    } else if (b < 152) {
        int bt = b - 128;
        int c = tid & 63, rg = tid >> 6;
        if (bt < 16) {
            // ---- Atilde (l,h) + col-bias b~ ----
            int l = bt >> 2, h = bt & 3;
            float (*smK)[65] = (float(*)[65])sm;
            float acc[8];
#pragma unroll
            for (int u = 0; u < 8; u++) acc[u] = 0.f;
            float bacc = 0.f;
            for (int d0 = 0; d0 < DH_; d0 += 64) {
                __syncthreads();
                for (int idx = tid; idx < 4096; idx += 512) {
                    int cc = idx >> 6, d = idx & 63;
                    smK[cc][d] = kpW[l * (D_ * HD_) + cc * HD_ + h * DH_ + d0 + d];
                }
                __syncthreads();
                const float* qp = qpW + l * (D_ * HD_) + h * DH_ + d0;
                const float* qb = qpB + l * HD_ + h * DH_ + d0;
#pragma unroll 4
                for (int d = 0; d < 64; d++) {
                    float w = smK[c][d];
#pragma unroll
                    for (int u = 0; u < 8; u++) acc[u] += qp[(rg * 8 + u) * HD_ + d] * w;
                    if (rg == 0) bacc += w * qb[d];
                }
            }
            const float s = 0.08838834764831843f;  // 1/sqrt(128)
#pragma unroll
            for (int u = 0; u < 8; u++)
                g_At[((l * H_ + h) * D_ + rg * 8 + u) * D_ + c] = acc[u] * s;
            if (rg == 0) g_bt[(l * H_ + h) * D_ + c] = bacc * s;
        } else {
            // ---- M (l,qk) + v ----
            int l = (bt - 16) >> 1, qk = (bt - 16) & 1;
            const float* Wp  = (qk ? kpW : qpW) + l * D_ * HD_;
            const float* WpB = (qk ? kpB : qpB) + l * HD_;
            const float* Wo  = (qk ? koW : qoW) + l * HD_ * D_;
            const float* WoB = (qk ? koB : qoB) + l * D_;
            float (*smP)[65] = (float(*)[65])sm;
            float acc[8];
#pragma unroll
            for (int u = 0; u < 8; u++) acc[u] = 0.f;
            float vacc = 0.f;
            for (int s0 = 0; s0 < HD_; s0 += 64) {
                __syncthreads();
                for (int idx = tid; idx < 4096; idx += 512) {
                    int dd = idx >> 6, ss = idx & 63;
                    smP[dd][ss] = Wp[dd * HD_ + s0 + ss];
                }
                __syncthreads();
#pragma unroll 4
                for (int ss = 0; ss < 64; ss++) {
                    int s = s0 + ss;
                    int m = ((s & 127) << 2) | (s >> 7);   // inverse head/dh permutation
                    float w = Wo[m * D_ + c];
#pragma unroll
                    for (int u = 0; u < 8; u++) acc[u] += smP[rg * 8 + u][ss] * w;
                    if (rg == 0) vacc += WpB[s] * w;
                }
            }
#pragma unroll
            for (int u = 0; u < 8; u++)
                g_M[((l * 2 + qk) * D_ + rg * 8 + u) * D_ + c] = acc[u];
            if (rg == 0) g_v[(l * 2 + qk) * D_ + c] = vacc + WoB[c];
        }
    }
    gridBar();

    // ===== Phase 1: blocks 0-223: bias pipeline ; 224-287: full 4-layer A-chain =====
    if (b < 224) {
        float (*beta)[BD_]  = (float(*)[BD_])sm;                 // 2 KB
        float (*sb)[HBD_]   = (float(*)[HBD_])(sm + 2048);       // 8 KB
        float (*parts)[512] = (float(*)[512])(sm + 10240);       // 8 KB
        int*   svp          = (int*)(sm + 18432);
        float* sd           = (float*)(sm + 18464);
        int total = g_pairCount + 1;
        int nChunks = (total + 3) >> 2;
        for (int ch = b; ch < nChunks; ch += 224) {
            int pbase = ch << 2;
            int np = total - pbase; if (np > 4) np = 4;
            if (tid < 4) {
                int vp = pbase + tid;
                if (tid < np) {
                    if (vp == 0) { svp[tid] = -1; sd[tid] = 0.f; }
                    else { int pr = g_pairList[vp - 1]; svp[tid] = pr; sd[tid] = g_d[pr]; }
                } else { svp[tid] = -2; sd[tid] = 0.f; }
            }
            __syncthreads();
            {
                int p = tid >> 7, c = tid & 127;
                float ddv = sd[p] - (float)c * (1.0f / 127.0f);
                beta[p][c] = (p < np && svp[p] >= 0) ? expf(-127.0f * ddv * ddv) : 0.f;
            }
            __syncthreads();
            for (int l = 0; l < L_; l++) {
                // GEMV1: coalesced weight loads, float4 smem operand, 4 c per iter
                const float* W = bpW + l * BD_ * HBD_;
                const float4* b0p = (const float4*)beta[0];
                const float4* b1p = (const float4*)beta[1];
                const float4* b2p = (const float4*)beta[2];
                const float4* b3p = (const float4*)beta[3];
                float acc0 = 0.f, acc1 = 0.f, acc2 = 0.f, acc3 = 0.f;
#pragma unroll 8
                for (int c4 = 0; c4 < 32; c4++) {
                    const float* wb = W + (4 * c4) * HBD_ + tid;
                    float w0 = wb[0], w1 = wb[HBD_], w2 = wb[2 * HBD_], w3 = wb[3 * HBD_];
                    float4 x0 = b0p[c4], x1 = b1p[c4], x2 = b2p[c4], x3 = b3p[c4];
                    acc0 += w0 * x0.x + w1 * x0.y + w2 * x0.z + w3 * x0.w;
                    acc1 += w0 * x1.x + w1 * x1.y + w2 * x1.z + w3 * x1.w;
                    acc2 += w0 * x2.x + w1 * x2.y + w2 * x2.z + w3 * x2.w;
                    acc3 += w0 * x3.x + w1 * x3.y + w2 * x3.z + w3 * x3.w;
                }
                float bb = bpB[l * HBD_ + tid];
                sb[0][tid] = acc0 + bb;
                sb[1][tid] = acc1 + bb;
                sb[2][tid] = acc2 + bb;
                sb[3][tid] = acc3 + bb;
                __syncthreads();
                if (tid < 16) {
                    int p = tid >> 2, h = tid & 3;
                    if (p < np && svp[p] != -2) {
                        const float4* sp4 = (const float4*)(sb[p] + h * BD_);
                        float s = 0.f;
#pragma unroll 8
                        for (int k = 0; k < 32; k++) {
                            float4 v = sp4[k];
                            s += v.x * v.x + v.y * v.y + v.z * v.z + v.w * v.w;
                        }
                        float r = sqrtf(s);
                        if (svp[p] == -1) g_cdiffs[l * H_ + h] = r;
                        else              g_diffs[(l * H_ + h) * (N_ * N_) + svp[p]] = r;
                    }
                }
                if (l < L_ - 1) {
                    // GEMV2: coalesced weight loads, float4 broadcast smem, 4 o per iter
                    int c = tid & 127, os = tid >> 7;
                    const float* W2 = bowW + l * HBD_ * BD_ + c;
                    const float4* s0p = (const float4*)sb[0] + os * 32;
                    const float4* s1p = (const float4*)sb[1] + os * 32;
                    const float4* s2p = (const float4*)sb[2] + os * 32;
                    const float4* s3p = (const float4*)sb[3] + os * 32;
                    float a0 = 0.f, a1 = 0.f, a2 = 0.f, a3 = 0.f;
#pragma unroll 8
                    for (int k = 0; k < 32; k++) {
                        const float* wb = W2 + (os * 128 + 4 * k) * BD_;
                        float w0 = wb[0], w1 = wb[BD_], w2 = wb[2 * BD_], w3 = wb[3 * BD_];
                        float4 y0 = s0p[k], y1 = s1p[k], y2 = s2p[k], y3 = s3p[k];
                        a0 += w0 * y0.x + w1 * y0.y + w2 * y0.z + w3 * y0.w;
                        a1 += w0 * y1.x + w1 * y1.y + w2 * y1.z + w3 * y1.w;
                        a2 += w0 * y2.x + w1 * y2.y + w2 * y2.z + w3 * y2.w;
                        a3 += w0 * y3.x + w1 * y3.y + w2 * y3.z + w3 * y3.w;
                    }
                    parts[os][0 * BD_ + c] = a0;
                    parts[os][1 * BD_ + c] = a1;
                    parts[os][2 * BD_ + c] = a2;
                    parts[os][3 * BD_ + c] = a3;
                    __syncthreads();
                    int p = tid >> 7, cc = tid & 127;
                    float v = parts[0][p * BD_ + cc] + parts[1][p * BD_ + cc]
                            + parts[2][p * BD_ + cc] + parts[3][p * BD_ + cc]
                            + bowB[l * BD_ + cc];
                    beta[p][cc] = mishf(v);
                }
                __syncthreads();
            }
            __syncthreads();
        }
    } else {
        // -------- A-chain: 8 rows per block, all 4 layers, row-local --------
        float (*sq)[D_]  = (float(*)[D_])sm;
        float (*srs)[D_] = (float(*)[D_])(sm + 2048);
        float (*srq)[D_] = (float(*)[D_])(sm + 4096);
        int ab = b - 224; bool isK = ab >= 32; int r0 = (ab & 31) * 8;
        int rr = tid >> 6, c = tid & 63, row = r0 + rr;
        sq[rr][c] = (isK ? g_k : g_q)[row * D_ + c];
        __syncthreads();
        for (int l = 0; l < L_; l++) {
            float au = 0.f;
            if (!isK) {
                const float* A0 = g_At + ((l * H_ + 0) * D_) * D_;
                const float* A1 = g_At + ((l * H_ + 1) * D_) * D_;
                const float* A2 = g_At + ((l * H_ + 2) * D_) * D_;
                const float* A3 = g_At + ((l * H_ + 3) * D_) * D_;
                const float* Mq = g_M + (l * 2 + 0) * D_ * D_;
                float b0 = 0, b1 = 0, b2 = 0, b3 = 0;
#pragma unroll 8
                for (int d = 0; d < D_; d++) {
                    float qv = sq[rr][d];
                    b0 += qv * A0[d * D_ + c];
                    b1 += qv * A1[d * D_ + c];
                    b2 += qv * A2[d * D_ + c];
                    b3 += qv * A3[d * D_ + c];
                    au += qv * Mq[d * D_ + c];
                }
                g_B[((l * H_ + 0) * N_ + row) * D_ + c] = b0;
                g_B[((l * H_ + 1) * N_ + row) * D_ + c] = b1;
                g_B[((l * H_ + 2) * N_ + row) * D_ + c] = b2;
                g_B[((l * H_ + 3) * N_ + row) * D_ + c] = b3;
                au += g_v[(l * 2 + 0) * D_ + c];
            } else {
                const float* Mk = g_M + (l * 2 + 1) * D_ * D_;
#pragma unroll 8
                for (int d = 0; d < D_; d++) au += sq[rr][d] * Mk[d * D_ + c];
                au += g_v[(l * 2 + 1) * D_ + c];
                ((float*)g_kT4)[((l * 16 + (c >> 2)) * N_ + row) * 4 + (c & 3)] = sq[rr][c];
                if (c < 4) {
                    const float* bt = g_bt + (l * H_ + c) * D_;
                    float s = 0.f;
#pragma unroll 8
                    for (int d = 0; d < D_; d++) s += sq[rr][d] * bt[d];
                    g_colK[(l * H_ + c) * N_ + row] = s;
                }
            }
            if (l < L_ - 1) {
                float y = sq[rr][c] + mishf(au);
                srs[rr][c] = y; srq[rr][c] = y * y;
                __syncthreads();
                for (int s = 32; s > 0; s >>= 1) {
                    if (c < s) { srs[rr][c] += srs[rr][c + s]; srq[rr][c] += srq[rr][c + s]; }
                    __syncthreads();
                }
                const float* G  = (isK ? klnG : qlnG) + l * D_;
                const float* Bt = (isK ? klnB : qlnB) + l * D_;
                float mean = srs[rr][0] * (1.0f / 64.0f);
                float var  = srq[rr][0] * (1.0f / 64.0f) - mean * mean;
                float o = (y - mean) * rsqrtf(var + EPS_) * G[c] + Bt[c];
                __syncthreads();
                sq[rr][c] = o;
                __syncthreads();
            }
        }
    }
    gridBar();

    // ====== Phase 2: 512 (l,h,tile8) softmax units, fully parallel, grid-stride =====
    {
        float (*sB)[D_]   = (float(*)[D_])sm;                     // 2 KB
        float4 (*sB4)[16] = (float4(*)[16])sm;
        float (*parts)[8][256] = (float(*)[8][256])(sm + 2048);   // 16 KB
        for (int u = b; u < 512; u += G_) {
            int l = u >> 7, h = (u >> 5) & 3, i0 = (u & 31) * 8;
            __syncthreads();
            sB[tid >> 6][tid & 63] =
                g_B[((l * H_ + h) * N_ + i0 + (tid >> 6)) * D_ + (tid & 63)];
            __syncthreads();
            int half = tid >> 8, j = tid & 255;
            float acc[8];
#pragma unroll
            for (int ii = 0; ii < 8; ii++) acc[ii] = 0.f;
            const float4* kt = g_kT4 + (l * 16 + half * 8) * N_ + j;
#pragma unroll
            for (int d4 = 0; d4 < 8; d4++) {
                float4 kv = kt[d4 * N_];
#pragma unroll
                for (int ii = 0; ii < 8; ii++) {
                    float4 q = sB4[ii][half * 8 + d4];
                    acc[ii] += q.x * kv.x + q.y * kv.y + q.z * kv.z + q.w * kv.w;
                }
            }
#pragma unroll
            for (int ii = 0; ii < 8; ii++) parts[half][ii][j] = acc[ii];
            __syncthreads();
            {
                // full-block merge: half 0 -> rows 0-3, half 1 -> rows 4-7
                float ck = g_colK[(l * H_ + h) * N_ + j];
                float cd = g_cdiffs[l * H_ + h];
                const float* dptr = g_diffs + (l * H_ + h) * (N_ * N_);
#pragma unroll
                for (int i2 = 0; i2 < 4; i2++) {
                    int ii = half * 4 + i2;
                    int pr = (i0 + ii) * N_ + j;
                    float dv = g_act[pr] ? dptr[pr] : cd;
                    parts[0][ii][j] = parts[0][ii][j] + parts[1][ii][j] + ck + dv;
                }
            }
            __syncthreads();
            int w = tid >> 5, lane = tid & 31;
            if (w < 8) {                          // warp w owns row i0+w
                int i = i0 + w;
                float a[8];
#pragma unroll
                for (int k = 0; k < 8; k++) a[k] = parts[0][w][k * 32 + lane];
                float mx = a[0];
#pragma unroll
                for (int k = 1; k < 8; k++) mx = fmaxf(mx, a[k]);
#pragma unroll
                for (int s = 16; s > 0; s >>= 1) mx = fmaxf(mx, __shfl_xor_sync(0xFFFFFFFFu, mx, s));
                float e[8], ssum = 0.f, vs = 0.f, eD = 0.f;
#pragma unroll
                for (int k = 0; k < 8; k++) {
                    e[k] = expf(a[k] - mx);
                    ssum += e[k];
                    int jj = k * 32 + lane;
                    vs += e[k] * nt[jj];
                    if (jj == i) eD = e[k];
                }
#pragma unroll
                for (int s = 16; s > 0; s >>= 1) {
                    ssum += __shfl_xor_sync(0xFFFFFFFFu, ssum, s);
                    vs   += __shfl_xor_sync(0xFFFFFFFFu, vs, s);
                    eD   += __shfl_xor_sync(0xFFFFFFFFu, eD, s);
                }
                if (lane == 0) {
                    float inv = 1.0f / ssum;
                    g_base[(l * H_ + h) * N_ + i] = (vs - eD * nt[i]) * inv;
                    g_w[(l * H_ + h) * N_ + i]    = eD * inv;
                }
            }
        }
    }
    gridBar();

    // ====== Phase 3: scalar affine fold over layers -> out ======
    if (b == 0) {
        if (tid < 256) {
            int i = tid;
            float p = g_pred0[i];
#pragma unroll
            for (int l = 0; l < L_; l++) {
                float s = 0.f;
#pragma unroll
                for (int h = 0; h < H_; h++)
                    s += g_base[(l * H_ + h) * N_ + i] + g_w[(l * H_ + h) * N_ + i] * p;
                p = 0.25f * s;
            }
            out[i] = p;
        }
        if (tid == 256) g_pairCount = 0;   // prep next replay
    }
}

// ---------------- launch ----------------
extern "C" void kernel_launch(void* const* d_in, const int* in_sizes, int n_in,
                              void* d_out, int out_size) {
    const float* X     = (const float*)d_in[0];
    const float* E     = (const float*)d_in[1];
    const float* nt    = (const float*)d_in[2];
    const float* embW  = (const float*)d_in[3];
    const float* embB  = (const float*)d_in[4];
    const float* boutW = (const float*)d_in[5];
    const float* boutB = (const float*)d_in[6];
    const float* qpW   = (const float*)d_in[7];
    const float* qpB   = (const float*)d_in[8];
    const float* kpW   = (const float*)d_in[9];
    const float* kpB   = (const float*)d_in[10];
    const float* qoW   = (const float*)d_in[11];
    const float* qoB   = (const float*)d_in[12];
    const float* koW   = (const float*)d_in[13];
    const float* koB   = (const float*)d_in[14];
    const float* bpW   = (const float*)d_in[15];
    const float* bpB   = (const float*)d_in[16];
    const float* bowW  = (const float*)d_in[17];
    const float* bowB  = (const float*)d_in[18];
    const float* qlnG  = (const float*)d_in[19];
    const float* qlnB  = (const float*)d_in[20];
    const float* klnG  = (const float*)d_in[21];
    const float* klnB  = (const float*)d_in[22];
    float* out = (float*)d_out;

    k_mega<<<G_, 512>>>(X, E, nt, embW, embB, boutW, boutB,
                        qpW, qpB, kpW, kpB, qoW, qoB, koW, koB,
                        bpW, bpB, bowW, bowB, qlnG, qlnB, klnG, klnB, out);
}